// round 17
// baseline (speedup 1.0000x reference)
#include <cuda_runtime.h>
#include <cstdint>

#define D_MODEL 512
#define KEY_DIM 128
#define BS_N 16
#define CTX_PER 1024
#define ARGS_PER 32
#define N_ARGS (BS_N * ARGS_PER)      /* 512  */
#define N_CTX  (BS_N * CTX_PER)       /* 16384 */
#define P_TOT  (N_ARGS * CTX_PER)     /* 524288 */

// Scratch (allocation-free rule: device globals). Device-side access only
// (host-side reference = host shadow symbol, the R3 bug).
// g_Qp holds TF32-ROUNDED values so logits-A needs no cvt.
__device__ float g_Qp[N_ARGS * D_MODEL];
__device__ float g_qb[N_ARGS];

// ---------------------------------------------------------------------------
__device__ __forceinline__ uint32_t f2tf32(float f) {
    uint32_t r;
    asm("cvt.rna.tf32.f32 %0, %1;" : "=r"(r) : "f"(f));
    return r;
}
__device__ __forceinline__ uint32_t bits2tf32(uint32_t b) {
    return f2tf32(__uint_as_float(b));
}

__device__ __forceinline__ void mma_tf32(float (&d)[4], const uint32_t (&a)[4],
                                         uint32_t b0, uint32_t b1) {
    asm volatile(
        "mma.sync.aligned.m16n8k8.row.col.f32.tf32.tf32.f32 "
        "{%0,%1,%2,%3}, {%4,%5,%6,%7}, {%8,%9}, {%0,%1,%2,%3};"
        : "+f"(d[0]), "+f"(d[1]), "+f"(d[2]), "+f"(d[3])
        : "r"(a[0]), "r"(a[1]), "r"(a[2]), "r"(a[3]), "r"(b0), "r"(b1));
}

__device__ __forceinline__ void ldsm_x4(uint32_t (&r)[4], uint32_t addr) {
    asm volatile(
        "ldmatrix.sync.aligned.m8n8.x4.shared.b16 {%0,%1,%2,%3}, [%4];"
        : "=r"(r[0]), "=r"(r[1]), "=r"(r[2]), "=r"(r[3]) : "r"(addr));
}

__device__ __forceinline__ uint32_t s2u(const void* p) {
    return (uint32_t)__cvta_generic_to_shared(p);
}
__device__ __forceinline__ void cp16(uint32_t smem_addr, const void* gmem) {
    asm volatile("cp.async.cg.shared.global [%0], [%1], 16;"
                 :: "r"(smem_addr), "l"(gmem));
}
__device__ __forceinline__ void cp_commit() {
    asm volatile("cp.async.commit_group;");
}
template<int N> __device__ __forceinline__ void cp_wait() {
    asm volatile("cp.async.wait_group %0;" :: "n"(N));
}
// PDL controls
__device__ __forceinline__ void pdl_trigger() {
    asm volatile("griddepcontrol.launch_dependents;");
}
__device__ __forceinline__ void pdl_wait() {
    asm volatile("griddepcontrol.wait;" ::: "memory");
}

// ===========================================================================
// LOGITS kernel (R16-proven shape; pre-wait section widened):
//   D[32 x 64] tile of Qp_s[32,512] @ C_s[64,512]^T + qb.
//   Grid (16,16), 128 thr = 2m x 2n warps (warp m16 x n32), S=4 cp.async
//   pipeline (stage = 32 k), compile-time stage slots, LDSM b16-view frags,
//   XOR-swizzled 128B rows.
//   BEFORE pdl_wait (input-independent, overlaps qp execution):
//     1. C stages 0..2 (3 cp.async groups)
//     2. rows-plane write (8 KB/CTA of the constant pattern p>>10)
//   AFTER pdl_wait: Q stages 0..2, drain, steady loop.
// ===========================================================================
__global__ __launch_bounds__(128, 4) void logits_tc(const float* __restrict__ Cm,
                                                    float* __restrict__ out,
                                                    float* __restrict__ rows_out) {
    constexpr int NST = 16;                         // 512 / 32
    constexpr int S   = 4;
    constexpr uint32_t QSTG = 32 * 32 * 4;          // 4 KB
    constexpr uint32_t CSTG = 64 * 32 * 4;          // 8 KB

    __shared__ float Qs[S * 32 * 32];               // 16 KB
    __shared__ float Cs[S * 64 * 32];               // 32 KB

    const int tid  = threadIdx.x;
    const int lane = tid & 31;
    const int warp = tid >> 5;
    const int wm   = warp >> 1;
    const int wn   = warp & 1;
    const int qr   = lane >> 2;
    const int qc   = lane & 3;

    const int qrow_base = blockIdx.y * 32;
    const int crow_base = blockIdx.y * CTX_PER + blockIdx.x * 64;
    const int ocol_base = blockIdx.x * 64;

    const uint32_t QsU = s2u(Qs);
    const uint32_t CsU = s2u(Cs);

    // ---- loader offsets
    const int lrow = tid >> 3;                      // 0..15
    const int lseg = tid & 7;
    const int lsw  = (lseg ^ (lrow & 7)) * 16;

    const float* qsrc0 = g_Qp + (size_t)(qrow_base + lrow)      * D_MODEL + lseg * 4;
    const float* qsrc1 = g_Qp + (size_t)(qrow_base + lrow + 16) * D_MODEL + lseg * 4;
    const uint32_t qoff0 = (uint32_t)(lrow * 128 + lsw);
    const uint32_t qoff1 = (uint32_t)((lrow + 16) * 128 + lsw);

    const float* csrc[4];
    uint32_t coff[4];
    #pragma unroll
    for (int j = 0; j < 4; j++) {
        int r = lrow + 16 * j;                      // 0..63
        csrc[j] = Cm + (size_t)(crow_base + r) * D_MODEL + lseg * 4;
        coff[j] = (uint32_t)(r * 128 + lsw);
    }

    // ---- LDSM per-kk byte offsets
    const int arow  = 16 * wm + (lane & 15);
    const int ahi   = lane >> 4;
    const int amask = arow & 7;
    const int browL = 32 * wn + (lane & 15);
    const int browH = browL + 16;
    const int bmask = browL & 7;
    uint32_t aoff[4], boffL[4], boffH[4];
    #pragma unroll
    for (int kk = 0; kk < 4; kk++) {
        aoff[kk]  = (uint32_t)(arow * 128 + (((kk * 2 + ahi) ^ amask) * 16));
        boffL[kk] = (uint32_t)(browL * 128 + (((kk * 2 + ahi) ^ bmask) * 16));
        boffH[kk] = (uint32_t)(browH * 128 + (((kk * 2 + ahi) ^ bmask) * 16));
    }

    float acc[4][4] = {};

    // ---- pre-wait 1: C stages 0..S-2 (independent of qp's output)
    #pragma unroll
    for (int s = 0; s < S - 1; s++) {
        #pragma unroll
        for (int j = 0; j < 4; j++)
            cp16(CsU + s * CSTG + coff[j], csrc[j] + s * 32);
        cp_commit();
    }

    // ---- pre-wait 2: rows plane (input-independent): 2048 floats per CTA
    if (rows_out) {
        const int base = (blockIdx.y * 16 + blockIdx.x) * 2048;
        float* dst = rows_out + base;
        #pragma unroll
        for (int i = 0; i < 4; i++) {
            int idx = tid * 4 + i * 512;
            float fr = (float)((base + idx) >> 10);
            *(float4*)(dst + idx) = make_float4(fr, fr, fr, fr);
        }
    }

    // ---- wait for qp kernel completion (g_Qp / g_qb now valid)
    pdl_wait();

    // ---- Q stages 0..S-2 (one group), then drain all
    #pragma unroll
    for (int s = 0; s < S - 1; s++) {
        cp16(QsU + s * QSTG + qoff0, qsrc0 + s * 32);
        cp16(QsU + s * QSTG + qoff1, qsrc1 + s * 32);
    }
    cp_commit();
    cp_wait<0>();
    __syncthreads();

    // ---- main loop: inner unroll x S -> compile-time stage slots
    #pragma unroll 1
    for (int itS = 0; itS < NST / S; itS++) {
        #pragma unroll
        for (int s = 0; s < S; s++) {
            const int st = itS * S + s;
            cp_wait<S - 2>();
            __syncthreads();

            const uint32_t qstage = QsU + s * QSTG;
            const uint32_t cstage = CsU + s * CSTG;
            #pragma unroll
            for (int kk = 0; kk < 4; kk++) {
                uint32_t a[4], bl[4], bh[4];
                ldsm_x4(a,  qstage + aoff[kk]);
                ldsm_x4(bl, cstage + boffL[kk]);
                ldsm_x4(bh, cstage + boffH[kk]);
                #pragma unroll
                for (int u = 0; u < 4; u++) {
                    bl[u] = bits2tf32(bl[u]);
                    bh[u] = bits2tf32(bh[u]);
                }
                mma_tf32(acc[0], a, bl[0], bl[2]);
                mma_tf32(acc[1], a, bl[1], bl[3]);
                mma_tf32(acc[2], a, bh[0], bh[2]);
                mma_tf32(acc[3], a, bh[1], bh[3]);
            }

            if (st + S - 1 < NST) {
                const int nb = (s + S - 1) & (S - 1);   // compile-time slot
                const int ks = (st + S - 1) * 32;
                cp16(QsU + nb * QSTG + qoff0, qsrc0 + ks);
                cp16(QsU + nb * QSTG + qoff1, qsrc1 + ks);
                #pragma unroll
                for (int j = 0; j < 4; j++)
                    cp16(CsU + nb * CSTG + coff[j], csrc[j] + ks);
            }
            cp_commit();
        }
    }

    // ---- epilogue: warp rows [16wm,+16), cols [32wn,+32)
    #pragma unroll
    for (int nt = 0; nt < 4; nt++) {
        #pragma unroll
        for (int half = 0; half < 2; half++) {
            const int rg = qrow_base + 16 * wm + qr + half * 8;
            const int col = ocol_base + 32 * wn + nt * 8 + qc * 2;
            const size_t off = (size_t)rg * CTX_PER + col;
            const float qb = g_qb[rg];
            *(float2*)(out + off) = make_float2(acc[nt][half * 2 + 0] + qb,
                                                acc[nt][half * 2 + 1] + qb);
        }
    }
}

// ===========================================================================
// QP kernel (proven R12/R16 GEMM + PDL trigger), slimmed: only g_Qp (tf32-
// rounded) + qb. rows plane moved to logits pre-wait. Grid (8,16), 128 thr.
// ===========================================================================
__global__ __launch_bounds__(128, 4) void qp_tc(const float* __restrict__ Qm,
                                                const float* __restrict__ Cm,
                                                const float* __restrict__ bv) {
    constexpr int NST = 4;
    constexpr int S   = 4;
    constexpr uint32_t QSTG = 32 * 32 * 4;
    constexpr uint32_t CSTG = 64 * 32 * 4;

    __shared__ float Qs[S * 32 * 32];
    __shared__ float Cs[S * 64 * 32];

    pdl_trigger();                      // let logits_tc start its pre-wait work

    const int tid  = threadIdx.x;
    const int lane = tid & 31;
    const int warp = tid >> 5;
    const int wm   = warp >> 1;
    const int wn   = warp & 1;
    const int qr   = lane >> 2;
    const int qc   = lane & 3;

    const int qrow_base = blockIdx.y * 32;
    const int crow_base = blockIdx.x * 64;
    const int ocol_base = blockIdx.x * 64;

    const uint32_t QsU = s2u(Qs);
    const uint32_t CsU = s2u(Cs);

    const int lrow = tid >> 3;
    const int lseg = tid & 7;
    const int lsw  = (lseg ^ (lrow & 7)) * 16;

    const float* qsrc0 = Qm + (size_t)(qrow_base + lrow)      * KEY_DIM + lseg * 4;
    const float* qsrc1 = Qm + (size_t)(qrow_base + lrow + 16) * KEY_DIM + lseg * 4;
    const uint32_t qoff0 = (uint32_t)(lrow * 128 + lsw);
    const uint32_t qoff1 = (uint32_t)((lrow + 16) * 128 + lsw);

    const float* csrc[4];
    uint32_t coff[4];
    #pragma unroll
    for (int j = 0; j < 4; j++) {
        int r = lrow + 16 * j;
        csrc[j] = Cm + (size_t)(crow_base + r) * KEY_DIM + lseg * 4;
        coff[j] = (uint32_t)(r * 128 + lsw);
    }

    const int arow  = 16 * wm + (lane & 15);
    const int ahi   = lane >> 4;
    const int amask = arow & 7;
    const int browL = 32 * wn + (lane & 15);
    const int browH = browL + 16;
    const int bmask = browL & 7;
    uint32_t aoff[4], boffL[4], boffH[4];
    #pragma unroll
    for (int kk = 0; kk < 4; kk++) {
        aoff[kk]  = (uint32_t)(arow * 128 + (((kk * 2 + ahi) ^ amask) * 16));
        boffL[kk] = (uint32_t)(browL * 128 + (((kk * 2 + ahi) ^ bmask) * 16));
        boffH[kk] = (uint32_t)(browH * 128 + (((kk * 2 + ahi) ^ bmask) * 16));
    }

    float acc[4][4] = {};

    #pragma unroll
    for (int s = 0; s < S - 1; s++) {
        cp16(QsU + s * QSTG + qoff0, qsrc0 + s * 32);
        cp16(QsU + s * QSTG + qoff1, qsrc1 + s * 32);
        #pragma unroll
        for (int j = 0; j < 4; j++)
            cp16(CsU + s * CSTG + coff[j], csrc[j] + s * 32);
        cp_commit();
    }

    #pragma unroll 1
    for (int itS = 0; itS < NST / S; itS++) {
        #pragma unroll
        for (int s = 0; s < S; s++) {
            const int st = itS * S + s;
            cp_wait<S - 2>();
            __syncthreads();

            const uint32_t qstage = QsU + s * QSTG;
            const uint32_t cstage = CsU + s * CSTG;
            #pragma unroll
            for (int kk = 0; kk < 4; kk++) {
                uint32_t a[4], bl[4], bh[4];
                ldsm_x4(a,  qstage + aoff[kk]);
                ldsm_x4(bl, cstage + boffL[kk]);
                ldsm_x4(bh, cstage + boffH[kk]);
                #pragma unroll
                for (int u = 0; u < 4; u++) {
                    a[u]  = bits2tf32(a[u]);
                    bl[u] = bits2tf32(bl[u]);
                    bh[u] = bits2tf32(bh[u]);
                }
                mma_tf32(acc[0], a, bl[0], bl[2]);
                mma_tf32(acc[1], a, bl[1], bl[3]);
                mma_tf32(acc[2], a, bh[0], bh[2]);
                mma_tf32(acc[3], a, bh[1], bh[3]);
            }

            if (st + S - 1 < NST) {
                const int nb = (s + S - 1) & (S - 1);
                const int ks = (st + S - 1) * 32;
                cp16(QsU + nb * QSTG + qoff0, qsrc0 + ks);
                cp16(QsU + nb * QSTG + qoff1, qsrc1 + ks);
                #pragma unroll
                for (int j = 0; j < 4; j++)
                    cp16(CsU + nb * CSTG + coff[j], csrc[j] + ks);
            }
            cp_commit();
        }
    }

    #pragma unroll
    for (int nt = 0; nt < 4; nt++) {
        #pragma unroll
        for (int half = 0; half < 2; half++) {
            const int rg = qrow_base + 16 * wm + qr + half * 8;
            const int col = ocol_base + 32 * wn + nt * 8 + qc * 2;
            *(float2*)(g_Qp + (size_t)rg * D_MODEL + col) =
                make_float2(__uint_as_float(f2tf32(acc[nt][half * 2 + 0])),
                            __uint_as_float(f2tf32(acc[nt][half * 2 + 1])));
        }
    }

    if (blockIdx.x == 0) {
        const int row = qrow_base + (tid >> 2);
        const int seg = tid & 3;
        const float* ap = Qm + (size_t)row * KEY_DIM + seg * 32;
        const float* bp = bv + seg * 32;
        float s = 0.f;
        #pragma unroll
        for (int k = 0; k < 8; k++) {
            float4 a  = *(const float4*)(ap + 4 * k);
            float4 bb = *(const float4*)(bp + 4 * k);
            s = fmaf(a.x, bb.x, s); s = fmaf(a.y, bb.y, s);
            s = fmaf(a.z, bb.z, s); s = fmaf(a.w, bb.w, s);
        }
        s += __shfl_xor_sync(0xffffffffu, s, 1);
        s += __shfl_xor_sync(0xffffffffu, s, 2);
        if (seg == 0) g_qb[row] = s;
    }
}

// ---------------------------------------------------------------------------
extern "C" void kernel_launch(void* const* d_in, const int* in_sizes, int n_in,
                              void* d_out, int out_size) {
    const float* argv = nullptr;
    const float* ctxv = nullptr;
    const float* Wm   = nullptr;
    const float* bv   = nullptr;
    int seen_65536 = 0;
    for (int i = 0; i < n_in; i++) {
        long sz = in_sizes[i];
        if (sz == (long)N_CTX * D_MODEL) {
            ctxv = (const float*)d_in[i];
        } else if (sz == (long)N_ARGS * KEY_DIM) {   // == D_MODEL*KEY_DIM too
            if (seen_65536++ == 0) argv = (const float*)d_in[i];
            else                   Wm   = (const float*)d_in[i];
        } else if (sz == KEY_DIM) {
            bv = (const float*)d_in[i];
        }
    }

    float* out        = (float*)d_out;
    float* rows_out   = nullptr;
    float* logits_out = out;
    if (out_size >= 2 * P_TOT) {        // (rows, logits) concatenated
        rows_out   = out;
        logits_out = out + P_TOT;
    }

    // Primary: Qp = arg @ W^T (+ qb only)
    qp_tc<<<dim3(8, 16), 128>>>(argv, Wm, bv);

    // Secondary (PDL): logits overlaps C prologue + rows-plane write with qp.
    cudaLaunchConfig_t cfg = {};
    cfg.gridDim  = dim3(16, 16);
    cfg.blockDim = dim3(128);
    cfg.dynamicSmemBytes = 0;
    cfg.stream = 0;
    cudaLaunchAttribute attrs[1];
    attrs[0].id = cudaLaunchAttributeProgrammaticStreamSerialization;
    attrs[0].val.programmaticStreamSerializationAllowed = 1;
    cfg.attrs = attrs;
    cfg.numAttrs = 1;
    cudaLaunchKernelEx(&cfg, logits_tc, ctxv, logits_out, rows_out);
}